// round 7
// baseline (speedup 1.0000x reference)
#include <cuda_runtime.h>

#define DIM 16
#define NLAYERS 3
#define LSTEPS 10
#define TPB 256

typedef unsigned long long u64;

// ---- packed f32x2 helpers (Blackwell sm_103a) ----
__device__ __forceinline__ u64 pk2(float a, float b){
    u64 r; asm("mov.b64 %0, {%1, %2};" : "=l"(r) : "f"(a), "f"(b)); return r;
}
__device__ __forceinline__ void up2(u64 v, float& a, float& b){
    asm("mov.b64 {%0, %1}, %2;" : "=f"(a), "=f"(b) : "l"(v));
}
__device__ __forceinline__ u64 fma2(u64 a, u64 b, u64 c){
    u64 d; asm("fma.rn.f32x2 %0, %1, %2, %3;" : "=l"(d) : "l"(a), "l"(b), "l"(c)); return d;
}
__device__ __forceinline__ u64 add2(u64 a, u64 b){
    u64 d; asm("add.rn.f32x2 %0, %1, %2;" : "=l"(d) : "l"(a), "l"(b)); return d;
}
__device__ __forceinline__ u64 mul2(u64 a, u64 b){
    u64 d; asm("mul.rn.f32x2 %0, %1, %2;" : "=l"(d) : "l"(a), "l"(b)); return d;
}

// fast tanh: (e-1)/(e+1), e = 2^(2y*log2(e)) — IDENTICAL ops to round 1
__device__ __forceinline__ float ftanh(float y){
    float z = fminf(y * 2.885390081777927f, 126.0f);
    float e; asm("ex2.approx.f32 %0, %1;" : "=f"(e) : "f"(z));
    float r; asm("rcp.approx.f32 %0, %1;" : "=f"(r) : "f"(e + 1.0f));
    return (e - 1.0f) * r;
}

#define ONE2_C  0x3F8000003F800000ULL
#define NONE2_C 0xBF800000BF800000ULL
#define HALF2_C 0x3F0000003F000000ULL

// Half-row matvec: acc[a] += sum_{k=0..15} x_k * M[k][off+2a .. off+2a+1]
// Same k-ascending fma order per output j as rounds 1-5 -> bitwise identical.
// xl = x[0..7], xh = x[8..15] (assembled from own half + partner half).
__device__ __forceinline__ void matvec_half(const float* __restrict__ Msh, int off,
                                            const float xl[8], const float xh[8],
                                            u64 acc[4]){
#pragma unroll
    for (int k = 0; k < 16; k++){
        float xk = (k < 8) ? xl[k] : xh[k - 8];
        u64 xkp = pk2(xk, xk);
        const ulonglong2* rp = reinterpret_cast<const ulonglong2*>(Msh + k*16 + off);
        ulonglong2 r0 = rp[0], r1 = rp[1];
        acc[0] = fma2(xkp, r0.x, acc[0]); acc[1] = fma2(xkp, r0.y, acc[1]);
        acc[2] = fma2(xkp, r1.x, acc[2]); acc[3] = fma2(xkp, r1.y, acc[3]);
    }
}

// exchange own 8 x's with partner (lane^1), build full-vector halves
__device__ __forceinline__ void exchange(const float xown[8], int half,
                                         float xl[8], float xh[8]){
    float tmp[8];
#pragma unroll
    for (int i = 0; i < 8; i++)
        tmp[i] = __shfl_xor_sync(0xffffffffu, xown[i], 1);
#pragma unroll
    for (int i = 0; i < 8; i++){
        xl[i] = half ? tmp[i]  : xown[i];
        xh[i] = half ? xown[i] : tmp[i];
    }
}

// f = (delta + x@M)*(1-x^2) on own 8 components; w=(1-x_own^2) precomputed by caller
__device__ __forceinline__ void forcev_half(const float* __restrict__ Msh,
                                            const float* __restrict__ dsh, int off,
                                            const float xl[8], const float xh[8],
                                            const u64 w[4], u64 f[4]){
    {
        const ulonglong2* dp = reinterpret_cast<const ulonglong2*>(dsh + off);
        ulonglong2 a = dp[0], b = dp[1];
        f[0] = a.x; f[1] = a.y; f[2] = b.x; f[3] = b.y;
    }
    matvec_half(Msh, off, xl, xh, f);
#pragma unroll
    for (int a = 0; a < 4; a++)
        f[a] = mul2(f[a], w[a]);
}

// Two threads per row (lane 2r: j 0-7, lane 2r+1: j 8-15).
// Persistent state per thread: yv4+vel4+f4 u64 -> ~60 regs peak, fits 64-reg
// ceiling at (256,4) = 32 warps/SM (2x R1) with NO spills.
__global__ void __launch_bounds__(TPB, 4)
ising_kernel(const float* __restrict__ Q, const float* __restrict__ delta,
             const float* __restrict__ y0, const float* __restrict__ vn,
             float* __restrict__ xout, float* __restrict__ energy, int B)
{
    __shared__ __align__(16) float Msh[DIM*DIM];
    __shared__ __align__(16) float dsh[DIM];
    int t = threadIdx.x;
    {
        int i = t >> 4, j = t & 15;
        float v = 0.f;
        if (i != j){
            int a = i > j ? i : j, b = i > j ? j : i;
            v = Q[a*(a-1)/2 + b];
        }
        Msh[t] = v;
        if (t < DIM) dsh[t] = delta[t];
    }
    __syncthreads();

    int gt   = blockIdx.x * TPB + t;
    int row  = gt >> 1;
    int half = gt & 1;
    int off  = half * 8;
    if (row >= B) return;   // never diverges: 2B % TPB == 0 for this problem

    // own 8 components of y0 (coalesced 32B per thread)
    u64 yv[4];
    {
        const ulonglong2* yp = reinterpret_cast<const ulonglong2*>(y0 + (size_t)row*16 + off);
        ulonglong2 a = yp[0], b = yp[1];
        yv[0] = a.x; yv[1] = a.y; yv[2] = b.x; yv[3] = b.y;
    }

    float xown[8];
#pragma unroll
    for (int i = 0; i < 4; i++){
        float lo, hi; up2(yv[i], lo, hi);
        xown[2*i] = ftanh(lo); xown[2*i+1] = ftanh(hi);
    }

    u64 f[4];
    {
        u64 w[4];
#pragma unroll
        for (int a = 0; a < 4; a++){
            u64 xp = pk2(xown[2*a], xown[2*a+1]);
            w[a] = fma2(mul2(xp, xp), NONE2_C, ONE2_C);
        }
        float xl[8], xh[8];
        exchange(xown, half, xl, xh);
        forcev_half(Msh, dsh, off, xl, xh, w, f);
    }

#pragma unroll 1
    for (int l = 0; l < NLAYERS; l++){
        u64 vel[4];
        {
            const ulonglong2* vp =
                reinterpret_cast<const ulonglong2*>(vn + ((size_t)l * B + row) * 16 + off);
            ulonglong2 a = vp[0], b = vp[1];
            vel[0] = a.x; vel[1] = a.y; vel[2] = b.x; vel[3] = b.y;
        }
#pragma unroll 1
        for (int it = 0; it < LSTEPS; it++){
#pragma unroll
            for (int i = 0; i < 4; i++){
                vel[i] = fma2(f[i], HALF2_C, vel[i]);   // vel + 0.5*f
                yv[i]  = add2(yv[i], vel[i]);           // y += vel_half
            }
            bool last = (l == NLAYERS-1) && (it == LSTEPS-1);
            if (!last){
#pragma unroll
                for (int i = 0; i < 4; i++){
                    float lo, hi; up2(yv[i], lo, hi);
                    xown[2*i] = ftanh(lo); xown[2*i+1] = ftanh(hi);
                }
                u64 w[4];
#pragma unroll
                for (int a = 0; a < 4; a++){
                    u64 xp = pk2(xown[2*a], xown[2*a+1]);
                    w[a] = fma2(mul2(xp, xp), NONE2_C, ONE2_C);
                }
                float xl[8], xh[8];
                exchange(xown, half, xl, xh);
                forcev_half(Msh, dsh, off, xl, xh, w, f);
#pragma unroll
                for (int i = 0; i < 4; i++)
                    vel[i] = fma2(f[i], HALF2_C, vel[i]);  // vel = vel_half + 0.5*f
            }
        }
    }

    // x_out = sign(y) with sign(0) -> -1, own 8 components
    float xo[8];
#pragma unroll
    for (int i = 0; i < 4; i++){
        float lo, hi; up2(yv[i], lo, hi);
        xo[2*i]   = lo > 0.f ? 1.f : -1.f;
        xo[2*i+1] = hi > 0.f ? 1.f : -1.f;
    }
    {
        float4* op = reinterpret_cast<float4*>(xout + (size_t)row*16 + off);
        op[0] = make_float4(xo[0], xo[1], xo[2], xo[3]);
        op[1] = make_float4(xo[4], xo[5], xo[6], xo[7]);
    }

    // energy = sum_j (0.5*(x@M)_j + delta_j)*x_j ; half-sums combined via shfl
    {
        float xl[8], xh[8];
        exchange(xo, half, xl, xh);
        u64 s[4] = {0ULL, 0ULL, 0ULL, 0ULL};
        matvec_half(Msh, off, xl, xh, s);
        const ulonglong2* dp = reinterpret_cast<const ulonglong2*>(dsh + off);
        ulonglong2 da = dp[0], db = dp[1];
        u64 dl[4] = {da.x, da.y, db.x, db.y};
        u64 acc = 0ULL;
#pragma unroll
        for (int a = 0; a < 4; a++){
            u64 tj = fma2(s[a], HALF2_C, dl[a]);
            u64 xp = pk2(xo[2*a], xo[2*a+1]);
            acc = fma2(tj, xp, acc);
        }
        float elo, ehi; up2(acc, elo, ehi);
        float part  = elo + ehi;
        float other = __shfl_xor_sync(0xffffffffu, part, 1);
        if (half == 0) energy[row] = part + other;
    }
}

extern "C" void kernel_launch(void* const* d_in, const int* in_sizes, int n_in,
                              void* d_out, int out_size)
{
    // metadata order: inputs(B,1), Q(120), delta(16), y0(B,16), vel_noise(3,B,16)
    const float* Q     = (const float*)d_in[1];
    const float* delta = (const float*)d_in[2];
    const float* y0    = (const float*)d_in[3];
    const float* vn    = (const float*)d_in[4];
    int B = in_sizes[3] / 16;

    float* out    = (float*)d_out;
    float* xout   = out;                      // (B, 16)
    float* energy = out + (size_t)B * 16;     // (B,)

    long long threads = 2LL * B;
    int grid = (int)((threads + TPB - 1) / TPB);
    ising_kernel<<<grid, TPB>>>(Q, delta, y0, vn, xout, energy, B);
}

// round 10
// speedup vs baseline: 2.1939x; 2.1939x over previous
#include <cuda_runtime.h>

#define DIM 16
#define NLAYERS 3
#define LSTEPS 10
#define TPB 128

typedef unsigned long long u64;

// ---- packed f32x2 helpers (Blackwell sm_103a) ----
__device__ __forceinline__ u64 pk2(float a, float b){
    u64 r; asm("mov.b64 %0, {%1, %2};" : "=l"(r) : "f"(a), "f"(b)); return r;
}
__device__ __forceinline__ void up2(u64 v, float& a, float& b){
    asm("mov.b64 {%0, %1}, %2;" : "=f"(a), "=f"(b) : "l"(v));
}
__device__ __forceinline__ u64 fma2(u64 a, u64 b, u64 c){
    u64 d; asm("fma.rn.f32x2 %0, %1, %2, %3;" : "=l"(d) : "l"(a), "l"(b), "l"(c)); return d;
}
__device__ __forceinline__ u64 add2(u64 a, u64 b){
    u64 d; asm("add.rn.f32x2 %0, %1, %2;" : "=l"(d) : "l"(a), "l"(b)); return d;
}
__device__ __forceinline__ u64 mul2(u64 a, u64 b){
    u64 d; asm("mul.rn.f32x2 %0, %1, %2;" : "=l"(d) : "l"(a), "l"(b)); return d;
}

// fast tanh: (e-1)/(e+1), e = 2^(2y*log2(e)) — IDENTICAL ops since round 1
__device__ __forceinline__ float ftanh(float y){
    float z = fminf(y * 2.885390081777927f, 126.0f);
    float e; asm("ex2.approx.f32 %0, %1;" : "=f"(e) : "f"(z));
    float r; asm("rcp.approx.f32 %0, %1;" : "=f"(r) : "f"(e + 1.0f));
    return (e - 1.0f) * r;
}

#define ONE2_C  0x3F8000003F800000ULL
#define NONE2_C 0xBF800000BF800000ULL
#define HALF2_C 0x3F0000003F000000ULL

// Half-row matvec: acc[a] += sum_{k=0..15} x_k * M[k][off+2a .. off+2a+1]
// Same k-ascending fma order per output j as rounds 1-7 -> bitwise identical.
// unroll capped at 8 to bound in-flight LDS regs (R5/R7 spill lesson).
__device__ __forceinline__ void matvec_half(const float* __restrict__ Msh, int off,
                                            const float xl[8], const float xh[8],
                                            u64 acc[4]){
#pragma unroll 8
    for (int k = 0; k < 16; k++){
        float xk = (k < 8) ? xl[k] : xh[k - 8];
        u64 xkp = pk2(xk, xk);
        const ulonglong2* rp = reinterpret_cast<const ulonglong2*>(Msh + k*16 + off);
        ulonglong2 r0 = rp[0], r1 = rp[1];
        acc[0] = fma2(xkp, r0.x, acc[0]); acc[1] = fma2(xkp, r0.y, acc[1]);
        acc[2] = fma2(xkp, r1.x, acc[2]); acc[3] = fma2(xkp, r1.y, acc[3]);
    }
}

// exchange own 8 x's with partner (lane^1), build full-vector halves
__device__ __forceinline__ void exchange(const float xown[8], int half,
                                         float xl[8], float xh[8]){
    float tmp[8];
#pragma unroll
    for (int i = 0; i < 8; i++)
        tmp[i] = __shfl_xor_sync(0xffffffffu, xown[i], 1);
#pragma unroll
    for (int i = 0; i < 8; i++){
        xl[i] = half ? tmp[i]  : xown[i];
        xh[i] = half ? xown[i] : tmp[i];
    }
}

// f = (delta + x@M)*(1-x^2) on own 8 components; w=(1-x_own^2) precomputed by caller
__device__ __forceinline__ void forcev_half(const float* __restrict__ Msh,
                                            const float* __restrict__ dsh, int off,
                                            const float xl[8], const float xh[8],
                                            const u64 w[4], u64 f[4]){
    {
        const ulonglong2* dp = reinterpret_cast<const ulonglong2*>(dsh + off);
        ulonglong2 a = dp[0], b = dp[1];
        f[0] = a.x; f[1] = a.y; f[2] = b.x; f[3] = b.y;
    }
    matvec_half(Msh, off, xl, xh, f);
#pragma unroll
    for (int a = 0; a < 4; a++)
        f[a] = mul2(f[a], w[a]);
}

// Two threads per row (lane 2r: j 0-7, lane 2r+1: j 8-15).
// R7 proved this bitwise-identical; R7's 64-reg cap spilled (regs pinned at 64,
// DRAM 16%). (128,5) -> 102-reg ceiling, 20 warps/SM, should hold ~90 live regs
// with NO spills and half of R1's per-thread LDS/MUFU/fma work.
__global__ void __launch_bounds__(TPB, 5)
ising_kernel(const float* __restrict__ Q, const float* __restrict__ delta,
             const float* __restrict__ y0, const float* __restrict__ vn,
             float* __restrict__ xout, float* __restrict__ energy, int B)
{
    __shared__ __align__(16) float Msh[DIM*DIM];
    __shared__ __align__(16) float dsh[DIM];
    int t = threadIdx.x;
#pragma unroll
    for (int idx = t; idx < 256; idx += TPB){
        int i = idx >> 4, j = idx & 15;
        float v = 0.f;
        if (i != j){
            int a = i > j ? i : j, b = i > j ? j : i;
            v = Q[a*(a-1)/2 + b];
        }
        Msh[idx] = v;
    }
    if (t < DIM) dsh[t] = delta[t];
    __syncthreads();

    int gt   = blockIdx.x * TPB + t;
    int row  = gt >> 1;
    int half = gt & 1;
    int off  = half * 8;
    if (row >= B) return;   // never diverges: 2B % TPB == 0 for this problem

    // own 8 components of y0 (coalesced 32B per thread)
    u64 yv[4];
    {
        const ulonglong2* yp = reinterpret_cast<const ulonglong2*>(y0 + (size_t)row*16 + off);
        ulonglong2 a = yp[0], b = yp[1];
        yv[0] = a.x; yv[1] = a.y; yv[2] = b.x; yv[3] = b.y;
    }

    float xown[8];
#pragma unroll
    for (int i = 0; i < 4; i++){
        float lo, hi; up2(yv[i], lo, hi);
        xown[2*i] = ftanh(lo); xown[2*i+1] = ftanh(hi);
    }

    u64 f[4];
    {
        u64 w[4];
#pragma unroll
        for (int a = 0; a < 4; a++){
            u64 xp = pk2(xown[2*a], xown[2*a+1]);
            w[a] = fma2(mul2(xp, xp), NONE2_C, ONE2_C);
        }
        float xl[8], xh[8];
        exchange(xown, half, xl, xh);
        forcev_half(Msh, dsh, off, xl, xh, w, f);
    }

#pragma unroll 1
    for (int l = 0; l < NLAYERS; l++){
        u64 vel[4];
        {
            const ulonglong2* vp =
                reinterpret_cast<const ulonglong2*>(vn + ((size_t)l * B + row) * 16 + off);
            ulonglong2 a = vp[0], b = vp[1];
            vel[0] = a.x; vel[1] = a.y; vel[2] = b.x; vel[3] = b.y;
        }
#pragma unroll 1
        for (int it = 0; it < LSTEPS; it++){
#pragma unroll
            for (int i = 0; i < 4; i++){
                vel[i] = fma2(f[i], HALF2_C, vel[i]);   // vel + 0.5*f
                yv[i]  = add2(yv[i], vel[i]);           // y += vel_half
            }
            bool last = (l == NLAYERS-1) && (it == LSTEPS-1);
            if (!last){
#pragma unroll
                for (int i = 0; i < 4; i++){
                    float lo, hi; up2(yv[i], lo, hi);
                    xown[2*i] = ftanh(lo); xown[2*i+1] = ftanh(hi);
                }
                u64 w[4];
#pragma unroll
                for (int a = 0; a < 4; a++){
                    u64 xp = pk2(xown[2*a], xown[2*a+1]);
                    w[a] = fma2(mul2(xp, xp), NONE2_C, ONE2_C);
                }
                float xl[8], xh[8];
                exchange(xown, half, xl, xh);
                forcev_half(Msh, dsh, off, xl, xh, w, f);
#pragma unroll
                for (int i = 0; i < 4; i++)
                    vel[i] = fma2(f[i], HALF2_C, vel[i]);  // vel = vel_half + 0.5*f
            }
        }
    }

    // x_out = sign(y) with sign(0) -> -1, own 8 components
    float xo[8];
#pragma unroll
    for (int i = 0; i < 4; i++){
        float lo, hi; up2(yv[i], lo, hi);
        xo[2*i]   = lo > 0.f ? 1.f : -1.f;
        xo[2*i+1] = hi > 0.f ? 1.f : -1.f;
    }
    {
        float4* op = reinterpret_cast<float4*>(xout + (size_t)row*16 + off);
        op[0] = make_float4(xo[0], xo[1], xo[2], xo[3]);
        op[1] = make_float4(xo[4], xo[5], xo[6], xo[7]);
    }

    // energy = sum_j (0.5*(x@M)_j + delta_j)*x_j ; half-sums combined via shfl
    {
        float xl[8], xh[8];
        exchange(xo, half, xl, xh);
        u64 s[4] = {0ULL, 0ULL, 0ULL, 0ULL};
        matvec_half(Msh, off, xl, xh, s);
        const ulonglong2* dp = reinterpret_cast<const ulonglong2*>(dsh + off);
        ulonglong2 da = dp[0], db = dp[1];
        u64 dl[4] = {da.x, da.y, db.x, db.y};
        u64 acc = 0ULL;
#pragma unroll
        for (int a = 0; a < 4; a++){
            u64 tj = fma2(s[a], HALF2_C, dl[a]);
            u64 xp = pk2(xo[2*a], xo[2*a+1]);
            acc = fma2(tj, xp, acc);
        }
        float elo, ehi; up2(acc, elo, ehi);
        float part  = elo + ehi;
        float other = __shfl_xor_sync(0xffffffffu, part, 1);
        if (half == 0) energy[row] = part + other;
    }
}

extern "C" void kernel_launch(void* const* d_in, const int* in_sizes, int n_in,
                              void* d_out, int out_size)
{
    // metadata order: inputs(B,1), Q(120), delta(16), y0(B,16), vel_noise(3,B,16)
    const float* Q     = (const float*)d_in[1];
    const float* delta = (const float*)d_in[2];
    const float* y0    = (const float*)d_in[3];
    const float* vn    = (const float*)d_in[4];
    int B = in_sizes[3] / 16;

    float* out    = (float*)d_out;
    float* xout   = out;                      // (B, 16)
    float* energy = out + (size_t)B * 16;     // (B,)

    long long threads = 2LL * B;
    int grid = (int)((threads + TPB - 1) / TPB);
    ising_kernel<<<grid, TPB>>>(Q, delta, y0, vn, xout, energy, B);
}

// round 11
// speedup vs baseline: 2.2576x; 1.0290x over previous
#include <cuda_runtime.h>

#define DIM 16
#define NLAYERS 3
#define LSTEPS 10
#define TPB 128

typedef unsigned long long u64;

// ---- packed f32x2 helpers (Blackwell sm_103a) ----
__device__ __forceinline__ u64 pk2(float a, float b){
    u64 r; asm("mov.b64 %0, {%1, %2};" : "=l"(r) : "f"(a), "f"(b)); return r;
}
__device__ __forceinline__ void up2(u64 v, float& a, float& b){
    asm("mov.b64 {%0, %1}, %2;" : "=f"(a), "=f"(b) : "l"(v));
}
__device__ __forceinline__ u64 fma2(u64 a, u64 b, u64 c){
    u64 d; asm("fma.rn.f32x2 %0, %1, %2, %3;" : "=l"(d) : "l"(a), "l"(b), "l"(c)); return d;
}
__device__ __forceinline__ u64 add2(u64 a, u64 b){
    u64 d; asm("add.rn.f32x2 %0, %1, %2;" : "=l"(d) : "l"(a), "l"(b)); return d;
}
__device__ __forceinline__ u64 mul2(u64 a, u64 b){
    u64 d; asm("mul.rn.f32x2 %0, %1, %2;" : "=l"(d) : "l"(a), "l"(b)); return d;
}

// fast tanh: (e-1)/(e+1), e = 2^(2y*log2(e)) — IDENTICAL ops since round 1
__device__ __forceinline__ float ftanh(float y){
    float z = fminf(y * 2.885390081777927f, 126.0f);
    float e; asm("ex2.approx.f32 %0, %1;" : "=f"(e) : "f"(z));
    float r; asm("rcp.approx.f32 %0, %1;" : "=f"(r) : "f"(e + 1.0f));
    return (e - 1.0f) * r;
}

#define ONE2_C  0x3F8000003F800000ULL
#define NONE2_C 0xBF800000BF800000ULL
#define HALF2_C 0x3F0000003F000000ULL

// Half-row matvec: acc[a] += sum_{k=0..15} x_k * M[k][off+2a .. off+2a+1]
// Same k-ascending fma order per output j as rounds 1-10 -> bitwise identical.
// unroll capped at 8 to bound in-flight LDS regs (R5/R7 spill lesson).
__device__ __forceinline__ void matvec_half(const float* __restrict__ Msh, int off,
                                            const float xl[8], const float xh[8],
                                            u64 acc[4]){
#pragma unroll 8
    for (int k = 0; k < 16; k++){
        float xk = (k < 8) ? xl[k] : xh[k - 8];
        u64 xkp = pk2(xk, xk);
        const ulonglong2* rp = reinterpret_cast<const ulonglong2*>(Msh + k*16 + off);
        ulonglong2 r0 = rp[0], r1 = rp[1];
        acc[0] = fma2(xkp, r0.x, acc[0]); acc[1] = fma2(xkp, r0.y, acc[1]);
        acc[2] = fma2(xkp, r1.x, acc[2]); acc[3] = fma2(xkp, r1.y, acc[3]);
    }
}

// exchange own 8 x's with partner (lane^1), build full-vector halves
__device__ __forceinline__ void exchange(const float xown[8], int half,
                                         float xl[8], float xh[8]){
    float tmp[8];
#pragma unroll
    for (int i = 0; i < 8; i++)
        tmp[i] = __shfl_xor_sync(0xffffffffu, xown[i], 1);
#pragma unroll
    for (int i = 0; i < 8; i++){
        xl[i] = half ? tmp[i]  : xown[i];
        xh[i] = half ? xown[i] : tmp[i];
    }
}

// f = (delta + x@M)*(1-x^2) on own 8 components; w=(1-x_own^2) precomputed by caller
__device__ __forceinline__ void forcev_half(const float* __restrict__ Msh,
                                            const float* __restrict__ dsh, int off,
                                            const float xl[8], const float xh[8],
                                            const u64 w[4], u64 f[4]){
    {
        const ulonglong2* dp = reinterpret_cast<const ulonglong2*>(dsh + off);
        ulonglong2 a = dp[0], b = dp[1];
        f[0] = a.x; f[1] = a.y; f[2] = b.x; f[3] = b.y;
    }
    matvec_half(Msh, off, xl, xh, f);
#pragma unroll
    for (int a = 0; a < 4; a++)
        f[a] = mul2(f[a], w[a]);
}

// Two threads per row (lane 2r: j 0-7, lane 2r+1: j 8-15).
// R10 measured 82 natural regs at the 102-cap -> the 6-CTA ceiling (85 regs)
// fits with margin: 24 warps/SM (+20% vs R10's 20), zero arithmetic change.
__global__ void __launch_bounds__(TPB, 6)
ising_kernel(const float* __restrict__ Q, const float* __restrict__ delta,
             const float* __restrict__ y0, const float* __restrict__ vn,
             float* __restrict__ xout, float* __restrict__ energy, int B)
{
    __shared__ __align__(16) float Msh[DIM*DIM];
    __shared__ __align__(16) float dsh[DIM];
    int t = threadIdx.x;
#pragma unroll
    for (int idx = t; idx < 256; idx += TPB){
        int i = idx >> 4, j = idx & 15;
        float v = 0.f;
        if (i != j){
            int a = i > j ? i : j, b = i > j ? j : i;
            v = Q[a*(a-1)/2 + b];
        }
        Msh[idx] = v;
    }
    if (t < DIM) dsh[t] = delta[t];
    __syncthreads();

    int gt   = blockIdx.x * TPB + t;
    int row  = gt >> 1;
    int half = gt & 1;
    int off  = half * 8;
    if (row >= B) return;   // never diverges: 2B % TPB == 0 for this problem

    // own 8 components of y0 (coalesced 32B per thread)
    u64 yv[4];
    {
        const ulonglong2* yp = reinterpret_cast<const ulonglong2*>(y0 + (size_t)row*16 + off);
        ulonglong2 a = yp[0], b = yp[1];
        yv[0] = a.x; yv[1] = a.y; yv[2] = b.x; yv[3] = b.y;
    }

    float xown[8];
#pragma unroll
    for (int i = 0; i < 4; i++){
        float lo, hi; up2(yv[i], lo, hi);
        xown[2*i] = ftanh(lo); xown[2*i+1] = ftanh(hi);
    }

    u64 f[4];
    {
        u64 w[4];
#pragma unroll
        for (int a = 0; a < 4; a++){
            u64 xp = pk2(xown[2*a], xown[2*a+1]);
            w[a] = fma2(mul2(xp, xp), NONE2_C, ONE2_C);
        }
        float xl[8], xh[8];
        exchange(xown, half, xl, xh);
        forcev_half(Msh, dsh, off, xl, xh, w, f);
    }

#pragma unroll 1
    for (int l = 0; l < NLAYERS; l++){
        u64 vel[4];
        {
            const ulonglong2* vp =
                reinterpret_cast<const ulonglong2*>(vn + ((size_t)l * B + row) * 16 + off);
            ulonglong2 a = vp[0], b = vp[1];
            vel[0] = a.x; vel[1] = a.y; vel[2] = b.x; vel[3] = b.y;
        }
#pragma unroll 1
        for (int it = 0; it < LSTEPS; it++){
#pragma unroll
            for (int i = 0; i < 4; i++){
                vel[i] = fma2(f[i], HALF2_C, vel[i]);   // vel + 0.5*f
                yv[i]  = add2(yv[i], vel[i]);           // y += vel_half
            }
            bool last = (l == NLAYERS-1) && (it == LSTEPS-1);
            if (!last){
#pragma unroll
                for (int i = 0; i < 4; i++){
                    float lo, hi; up2(yv[i], lo, hi);
                    xown[2*i] = ftanh(lo); xown[2*i+1] = ftanh(hi);
                }
                u64 w[4];
#pragma unroll
                for (int a = 0; a < 4; a++){
                    u64 xp = pk2(xown[2*a], xown[2*a+1]);
                    w[a] = fma2(mul2(xp, xp), NONE2_C, ONE2_C);
                }
                float xl[8], xh[8];
                exchange(xown, half, xl, xh);
                forcev_half(Msh, dsh, off, xl, xh, w, f);
#pragma unroll
                for (int i = 0; i < 4; i++)
                    vel[i] = fma2(f[i], HALF2_C, vel[i]);  // vel = vel_half + 0.5*f
            }
        }
    }

    // x_out = sign(y) with sign(0) -> -1, own 8 components
    float xo[8];
#pragma unroll
    for (int i = 0; i < 4; i++){
        float lo, hi; up2(yv[i], lo, hi);
        xo[2*i]   = lo > 0.f ? 1.f : -1.f;
        xo[2*i+1] = hi > 0.f ? 1.f : -1.f;
    }
    {
        float4* op = reinterpret_cast<float4*>(xout + (size_t)row*16 + off);
        op[0] = make_float4(xo[0], xo[1], xo[2], xo[3]);
        op[1] = make_float4(xo[4], xo[5], xo[6], xo[7]);
    }

    // energy = sum_j (0.5*(x@M)_j + delta_j)*x_j ; half-sums combined via shfl
    {
        float xl[8], xh[8];
        exchange(xo, half, xl, xh);
        u64 s[4] = {0ULL, 0ULL, 0ULL, 0ULL};
        matvec_half(Msh, off, xl, xh, s);
        const ulonglong2* dp = reinterpret_cast<const ulonglong2*>(dsh + off);
        ulonglong2 da = dp[0], db = dp[1];
        u64 dl[4] = {da.x, da.y, db.x, db.y};
        u64 acc = 0ULL;
#pragma unroll
        for (int a = 0; a < 4; a++){
            u64 tj = fma2(s[a], HALF2_C, dl[a]);
            u64 xp = pk2(xo[2*a], xo[2*a+1]);
            acc = fma2(tj, xp, acc);
        }
        float elo, ehi; up2(acc, elo, ehi);
        float part  = elo + ehi;
        float other = __shfl_xor_sync(0xffffffffu, part, 1);
        if (half == 0) energy[row] = part + other;
    }
}

extern "C" void kernel_launch(void* const* d_in, const int* in_sizes, int n_in,
                              void* d_out, int out_size)
{
    // metadata order: inputs(B,1), Q(120), delta(16), y0(B,16), vel_noise(3,B,16)
    const float* Q     = (const float*)d_in[1];
    const float* delta = (const float*)d_in[2];
    const float* y0    = (const float*)d_in[3];
    const float* vn    = (const float*)d_in[4];
    int B = in_sizes[3] / 16;

    float* out    = (float*)d_out;
    float* xout   = out;                      // (B, 16)
    float* energy = out + (size_t)B * 16;     // (B,)

    long long threads = 2LL * B;
    int grid = (int)((threads + TPB - 1) / TPB);
    ising_kernel<<<grid, TPB>>>(Q, delta, y0, vn, xout, energy, B);
}

// round 14
// speedup vs baseline: 2.2730x; 1.0068x over previous
#include <cuda_runtime.h>

#define DIM 16
#define NLAYERS 3
#define LSTEPS 10
#define TPB 128

typedef unsigned long long u64;

// ---- packed f32x2 helpers (Blackwell sm_103a) ----
__device__ __forceinline__ u64 pk2(float a, float b){
    u64 r; asm("mov.b64 %0, {%1, %2};" : "=l"(r) : "f"(a), "f"(b)); return r;
}
__device__ __forceinline__ void up2(u64 v, float& a, float& b){
    asm("mov.b64 {%0, %1}, %2;" : "=f"(a), "=f"(b) : "l"(v));
}
__device__ __forceinline__ u64 fma2(u64 a, u64 b, u64 c){
    u64 d; asm("fma.rn.f32x2 %0, %1, %2, %3;" : "=l"(d) : "l"(a), "l"(b), "l"(c)); return d;
}
__device__ __forceinline__ u64 add2(u64 a, u64 b){
    u64 d; asm("add.rn.f32x2 %0, %1, %2;" : "=l"(d) : "l"(a), "l"(b)); return d;
}
__device__ __forceinline__ u64 mul2(u64 a, u64 b){
    u64 d; asm("mul.rn.f32x2 %0, %1, %2;" : "=l"(d) : "l"(a), "l"(b)); return d;
}

#define ONE2_C  0x3F8000003F800000ULL
#define NONE2_C 0xBF800000BF800000ULL
#define HALF2_C 0x3F0000003F000000ULL
#define TANHC2_C 0x4038AA3B4038AA3BULL   // 2*log2(e) = 2.885390081777927 packed x2

// tanh tail from pre-multiplied z: (e-1)/(e+1), e = 2^z — same op chain since R1
// (the z = y*2log2(e) multiply now happens packed in the caller; lane-wise
//  mul.rn.f32x2 rounds identically to scalar FMUL -> bitwise identical)
__device__ __forceinline__ float ftanh_z(float z){
    z = fminf(z, 126.0f);
    float e; asm("ex2.approx.f32 %0, %1;" : "=f"(e) : "f"(z));
    float r; asm("rcp.approx.f32 %0, %1;" : "=f"(r) : "f"(e + 1.0f));
    return (e - 1.0f) * r;
}

// tanh of a packed pair: one mul2 + two scalar tails (saves 2 scalar FMULs/pair)
__device__ __forceinline__ void tanh_pair(u64 y2, float& xlo, float& xhi){
    u64 z2 = mul2(y2, TANHC2_C);
    float zlo, zhi; up2(z2, zlo, zhi);
    xlo = ftanh_z(zlo); xhi = ftanh_z(zhi);
}

// Half-row matvec: acc[a] += sum_{k=0..15} x_k * M[k][off+2a .. off+2a+1]
// Same k-ascending fma order per output j as rounds 1-11 -> bitwise identical.
__device__ __forceinline__ void matvec_half(const float* __restrict__ Msh, int off,
                                            const float xl[8], const float xh[8],
                                            u64 acc[4]){
#pragma unroll 8
    for (int k = 0; k < 16; k++){
        float xk = (k < 8) ? xl[k] : xh[k - 8];
        u64 xkp = pk2(xk, xk);
        const ulonglong2* rp = reinterpret_cast<const ulonglong2*>(Msh + k*16 + off);
        ulonglong2 r0 = rp[0], r1 = rp[1];
        acc[0] = fma2(xkp, r0.x, acc[0]); acc[1] = fma2(xkp, r0.y, acc[1]);
        acc[2] = fma2(xkp, r1.x, acc[2]); acc[3] = fma2(xkp, r1.y, acc[3]);
    }
}

// Indexed-shuffle exchange: even lane of each pair holds x[0..7], odd x[8..15].
// xl[i] = x[i] from even lane; xh[i] = x[8+i] from odd lane. No SELs, no tmp[].
// Values identical to the R7-R11 BFLY+SEL path -> bitwise identical.
__device__ __forceinline__ void exchange(const float xown[8], int lane_even, int lane_odd,
                                         float xl[8], float xh[8]){
#pragma unroll
    for (int i = 0; i < 8; i++){
        xl[i] = __shfl_sync(0xffffffffu, xown[i], lane_even);
        xh[i] = __shfl_sync(0xffffffffu, xown[i], lane_odd);
    }
}

// f = (delta + x@M)*(1-x^2) on own 8 components; w=(1-x_own^2) precomputed by caller
__device__ __forceinline__ void forcev_half(const float* __restrict__ Msh,
                                            const float* __restrict__ dsh, int off,
                                            const float xl[8], const float xh[8],
                                            const u64 w[4], u64 f[4]){
    {
        const ulonglong2* dp = reinterpret_cast<const ulonglong2*>(dsh + off);
        ulonglong2 a = dp[0], b = dp[1];
        f[0] = a.x; f[1] = a.y; f[2] = b.x; f[3] = b.y;
    }
    matvec_half(Msh, off, xl, xh, f);
#pragma unroll
    for (int a = 0; a < 4; a++)
        f[a] = mul2(f[a], w[a]);
}

// Two threads per row (lane 2r: j 0-7, lane 2r+1: j 8-15).
// R11: 80 regs, occ 36.6%, issue 80.3%, alu 52.7% == fma 52.5% -> issue-bound
// with alu at parity. This round cuts alu issue slots (SEL-free exchange,
// packed tanh premul); arithmetic values unchanged.
__global__ void __launch_bounds__(TPB, 6)
ising_kernel(const float* __restrict__ Q, const float* __restrict__ delta,
             const float* __restrict__ y0, const float* __restrict__ vn,
             float* __restrict__ xout, float* __restrict__ energy, int B)
{
    __shared__ __align__(16) float Msh[DIM*DIM];
    __shared__ __align__(16) float dsh[DIM];
    int t = threadIdx.x;
#pragma unroll
    for (int idx = t; idx < 256; idx += TPB){
        int i = idx >> 4, j = idx & 15;
        float v = 0.f;
        if (i != j){
            int a = i > j ? i : j, b = i > j ? j : i;
            v = Q[a*(a-1)/2 + b];
        }
        Msh[idx] = v;
    }
    if (t < DIM) dsh[t] = delta[t];
    __syncthreads();

    int gt   = blockIdx.x * TPB + t;
    int row  = gt >> 1;
    int half = gt & 1;
    int off  = half * 8;
    int lane = t & 31;
    int lane_even = lane & ~1;   // even lane of the pair: holds x[0..7]
    int lane_odd  = lane | 1;    // odd lane: holds x[8..15]
    if (row >= B) return;   // never diverges: 2B % TPB == 0 for this problem

    // own 8 components of y0 (coalesced 32B per thread)
    u64 yv[4];
    {
        const ulonglong2* yp = reinterpret_cast<const ulonglong2*>(y0 + (size_t)row*16 + off);
        ulonglong2 a = yp[0], b = yp[1];
        yv[0] = a.x; yv[1] = a.y; yv[2] = b.x; yv[3] = b.y;
    }

    float xown[8];
#pragma unroll
    for (int i = 0; i < 4; i++)
        tanh_pair(yv[i], xown[2*i], xown[2*i+1]);

    u64 f[4];
    {
        u64 w[4];
#pragma unroll
        for (int a = 0; a < 4; a++){
            u64 xp = pk2(xown[2*a], xown[2*a+1]);
            w[a] = fma2(mul2(xp, xp), NONE2_C, ONE2_C);
        }
        float xl[8], xh[8];
        exchange(xown, lane_even, lane_odd, xl, xh);
        forcev_half(Msh, dsh, off, xl, xh, w, f);
    }

#pragma unroll 1
    for (int l = 0; l < NLAYERS; l++){
        u64 vel[4];
        {
            const ulonglong2* vp =
                reinterpret_cast<const ulonglong2*>(vn + ((size_t)l * B + row) * 16 + off);
            ulonglong2 a = vp[0], b = vp[1];
            vel[0] = a.x; vel[1] = a.y; vel[2] = b.x; vel[3] = b.y;
        }
#pragma unroll 1
        for (int it = 0; it < LSTEPS; it++){
#pragma unroll
            for (int i = 0; i < 4; i++){
                vel[i] = fma2(f[i], HALF2_C, vel[i]);   // vel + 0.5*f
                yv[i]  = add2(yv[i], vel[i]);           // y += vel_half
            }
            bool last = (l == NLAYERS-1) && (it == LSTEPS-1);
            if (!last){
                float xl[8], xh[8];
#pragma unroll
                for (int i = 0; i < 4; i++)
                    tanh_pair(yv[i], xown[2*i], xown[2*i+1]);
                u64 w[4];
#pragma unroll
                for (int a = 0; a < 4; a++){
                    u64 xp = pk2(xown[2*a], xown[2*a+1]);
                    w[a] = fma2(mul2(xp, xp), NONE2_C, ONE2_C);
                }
                exchange(xown, lane_even, lane_odd, xl, xh);
                forcev_half(Msh, dsh, off, xl, xh, w, f);
#pragma unroll
                for (int i = 0; i < 4; i++)
                    vel[i] = fma2(f[i], HALF2_C, vel[i]);  // vel = vel_half + 0.5*f
            }
        }
    }

    // x_out = sign(y) with sign(0) -> -1, own 8 components
    float xo[8];
#pragma unroll
    for (int i = 0; i < 4; i++){
        float lo, hi; up2(yv[i], lo, hi);
        xo[2*i]   = lo > 0.f ? 1.f : -1.f;
        xo[2*i+1] = hi > 0.f ? 1.f : -1.f;
    }
    {
        float4* op = reinterpret_cast<float4*>(xout + (size_t)row*16 + off);
        op[0] = make_float4(xo[0], xo[1], xo[2], xo[3]);
        op[1] = make_float4(xo[4], xo[5], xo[6], xo[7]);
    }

    // energy = sum_j (0.5*(x@M)_j + delta_j)*x_j ; half-sums combined via shfl
    {
        float xl[8], xh[8];
        exchange(xo, lane_even, lane_odd, xl, xh);
        u64 s[4] = {0ULL, 0ULL, 0ULL, 0ULL};
        matvec_half(Msh, off, xl, xh, s);
        const ulonglong2* dp = reinterpret_cast<const ulonglong2*>(dsh + off);
        ulonglong2 da = dp[0], db = dp[1];
        u64 dl[4] = {da.x, da.y, db.x, db.y};
        u64 acc = 0ULL;
#pragma unroll
        for (int a = 0; a < 4; a++){
            u64 tj = fma2(s[a], HALF2_C, dl[a]);
            u64 xp = pk2(xo[2*a], xo[2*a+1]);
            acc = fma2(tj, xp, acc);
        }
        float elo, ehi; up2(acc, elo, ehi);
        float part  = elo + ehi;
        float other = __shfl_xor_sync(0xffffffffu, part, 1);
        if (half == 0) energy[row] = part + other;
    }
}

extern "C" void kernel_launch(void* const* d_in, const int* in_sizes, int n_in,
                              void* d_out, int out_size)
{
    // metadata order: inputs(B,1), Q(120), delta(16), y0(B,16), vel_noise(3,B,16)
    const float* Q     = (const float*)d_in[1];
    const float* delta = (const float*)d_in[2];
    const float* y0    = (const float*)d_in[3];
    const float* vn    = (const float*)d_in[4];
    int B = in_sizes[3] / 16;

    float* out    = (float*)d_out;
    float* xout   = out;                      // (B, 16)
    float* energy = out + (size_t)B * 16;     // (B,)

    long long threads = 2LL * B;
    int grid = (int)((threads + TPB - 1) / TPB);
    ising_kernel<<<grid, TPB>>>(Q, delta, y0, vn, xout, energy, B);
}